// round 1
// baseline (speedup 1.0000x reference)
#include <cuda_runtime.h>
#include <cuda_bf16.h>
#include <cstddef>

#define N_NODES 40000
#define N_EDGES 640000
#define IN_F    256
#define EDGE_F  64
#define OUT_F   128
#define NH      8
#define DH      16

// ---------------- scratch (static __device__ allocations; no cudaMalloc) ----------------
__device__ float g_Wh[(size_t)N_NODES * OUT_F];        // 20.5 MB
__device__ float g_ssrc[N_NODES * NH];                 // s_src per node/head
__device__ float g_sdst[N_NODES * NH];                 // s_dst per node/head
__device__ float g_se[(size_t)N_EDGES * NH];           // s_e per edge/head (incl. b_eff)
__device__ float g_sval[(size_t)N_EDGES * NH];         // sorted (s_src[src]+s_e) per slot
__device__ int   g_ssidx[N_EDGES];                     // sorted src index per slot
__device__ int   g_count[N_NODES];
__device__ int   g_rowstart[N_NODES + 1];
__device__ int   g_cursor[N_NODES];
__device__ float g_weff[NH * EDGE_F];
__device__ float g_beff[NH];

// ---------------- K0: init (zero histogram, fold attn into edge_w) ----------------
__global__ void k_init(const float* __restrict__ edge_w,
                       const float* __restrict__ edge_b,
                       const float* __restrict__ attn) {
    int t = blockIdx.x * blockDim.x + threadIdx.x;
    for (int i = t; i < N_NODES; i += gridDim.x * blockDim.x) g_count[i] = 0;
    if (blockIdx.x == 0) {
        // w_eff[h,k] = sum_d edge_w[(h*16+d),k] * a_e[h,d]   (a_e = attn[h, 32:48])
        for (int i = threadIdx.x; i < NH * EDGE_F; i += blockDim.x) {
            int h = i >> 6, k = i & 63;
            float s = 0.f;
            #pragma unroll
            for (int d = 0; d < DH; d++)
                s += edge_w[(h * DH + d) * EDGE_F + k] * attn[h * 48 + 32 + d];
            g_weff[i] = s;
        }
        if (threadIdx.x < NH) {
            int h = threadIdx.x;
            float s = 0.f;
            #pragma unroll
            for (int d = 0; d < DH; d++)
                s += edge_b[h * DH + d] * attn[h * 48 + 32 + d];
            g_beff[h] = s;
        }
    }
}

// ---------------- K1: Wh = node_feats @ node_w.T + node_b (fp32 SIMT GEMM) ----------------
// Tile 128x128, K-step 16, 256 threads, 8x8 register micro-tiles.
__global__ __launch_bounds__(256) void k_gemm(const float* __restrict__ A,
                                              const float* __restrict__ B,
                                              const float* __restrict__ bias) {
    __shared__ float As[16][128];
    __shared__ float Bs[16][128];
    int tid = threadIdx.x;
    int m0 = blockIdx.x * 128;
    int tm = (tid >> 4) * 8;   // row offset in tile
    int tn = (tid & 15) * 8;   // col offset in tile

    float acc[8][8];
    #pragma unroll
    for (int i = 0; i < 8; i++)
        #pragma unroll
        for (int j = 0; j < 8; j++) acc[i][j] = 0.f;

    for (int k0 = 0; k0 < IN_F; k0 += 16) {
        // cooperative loads: 128 rows x 16 k  (512 float4, 2 per thread), transposed into smem
        #pragma unroll
        for (int t = 0; t < 2; t++) {
            int idx = tid * 2 + t;            // 0..511
            int row = idx >> 2;
            int kq  = (idx & 3) * 4;
            float4 v = make_float4(0.f, 0.f, 0.f, 0.f);
            if (m0 + row < N_NODES)
                v = *reinterpret_cast<const float4*>(&A[(size_t)(m0 + row) * IN_F + k0 + kq]);
            As[kq + 0][row] = v.x; As[kq + 1][row] = v.y;
            As[kq + 2][row] = v.z; As[kq + 3][row] = v.w;
            float4 w = *reinterpret_cast<const float4*>(&B[(size_t)row * IN_F + k0 + kq]);
            Bs[kq + 0][row] = w.x; Bs[kq + 1][row] = w.y;
            Bs[kq + 2][row] = w.z; Bs[kq + 3][row] = w.w;
        }
        __syncthreads();
        #pragma unroll
        for (int kk = 0; kk < 16; kk++) {
            float a[8], b[8];
            *reinterpret_cast<float4*>(a)     = *reinterpret_cast<float4*>(&As[kk][tm]);
            *reinterpret_cast<float4*>(a + 4) = *reinterpret_cast<float4*>(&As[kk][tm + 4]);
            *reinterpret_cast<float4*>(b)     = *reinterpret_cast<float4*>(&Bs[kk][tn]);
            *reinterpret_cast<float4*>(b + 4) = *reinterpret_cast<float4*>(&Bs[kk][tn + 4]);
            #pragma unroll
            for (int i = 0; i < 8; i++)
                #pragma unroll
                for (int j = 0; j < 8; j++) acc[i][j] += a[i] * b[j];
        }
        __syncthreads();
    }

    #pragma unroll
    for (int i = 0; i < 8; i++) {
        int m = m0 + tm + i;
        if (m < N_NODES) {
            float4 o0, o1;
            o0.x = acc[i][0] + bias[tn + 0]; o0.y = acc[i][1] + bias[tn + 1];
            o0.z = acc[i][2] + bias[tn + 2]; o0.w = acc[i][3] + bias[tn + 3];
            o1.x = acc[i][4] + bias[tn + 4]; o1.y = acc[i][5] + bias[tn + 5];
            o1.z = acc[i][6] + bias[tn + 6]; o1.w = acc[i][7] + bias[tn + 7];
            *reinterpret_cast<float4*>(&g_Wh[(size_t)m * OUT_F + tn])     = o0;
            *reinterpret_cast<float4*>(&g_Wh[(size_t)m * OUT_F + tn + 4]) = o1;
        }
    }
}

// ---------------- K2: per-node attention scores s_src, s_dst ----------------
__global__ void k_scores(const float* __restrict__ attn) {
    int t = blockIdx.x * blockDim.x + threadIdx.x;
    if (t >= N_NODES * NH) return;
    int n = t >> 3, h = t & 7;
    const float* w  = &g_Wh[(size_t)n * OUT_F + h * DH];
    const float* as = &attn[h * 48];
    const float* ad = as + DH;
    float s1 = 0.f, s2 = 0.f;
    #pragma unroll
    for (int d = 0; d < DH; d++) {
        float x = w[d];
        s1 += x * as[d];
        s2 += x * ad[d];
    }
    g_ssrc[t] = s1;
    g_sdst[t] = s2;
}

// ---------------- K3: s_e[e,h] = edge_feats[e] . w_eff[h] + b_eff[h]; dst histogram ----------------
__global__ __launch_bounds__(256) void k_se(const float* __restrict__ EF,
                                            const int* __restrict__ dst) {
    __shared__ float ws[NH * EDGE_F];
    __shared__ float bs[NH];
    for (int i = threadIdx.x; i < NH * EDGE_F; i += blockDim.x) ws[i] = g_weff[i];
    if (threadIdx.x < NH) bs[threadIdx.x] = g_beff[threadIdx.x];
    __syncthreads();

    int e = blockIdx.x * blockDim.x + threadIdx.x;
    if (e >= N_EDGES) return;

    float acc[NH];
    #pragma unroll
    for (int h = 0; h < NH; h++) acc[h] = bs[h];

    const float4* ef = reinterpret_cast<const float4*>(EF + (size_t)e * EDGE_F);
    #pragma unroll
    for (int g = 0; g < EDGE_F / 4; g++) {
        float4 x = ef[g];
        #pragma unroll
        for (int h = 0; h < NH; h++) {
            float4 w = *reinterpret_cast<const float4*>(&ws[h * EDGE_F + g * 4]);
            acc[h] += x.x * w.x + x.y * w.y + x.z * w.z + x.w * w.w;
        }
    }
    atomicAdd(&g_count[dst[e]], 1);
    float4* o = reinterpret_cast<float4*>(&g_se[(size_t)e * NH]);
    o[0] = make_float4(acc[0], acc[1], acc[2], acc[3]);
    o[1] = make_float4(acc[4], acc[5], acc[6], acc[7]);
}

// ---------------- K4: exclusive scan of counts -> row_start, cursor (single block) ----------------
__global__ __launch_bounds__(1024) void k_scan() {
    __shared__ int warpsums[32];
    __shared__ int carry_s;
    int tid = threadIdx.x;
    int lane = tid & 31, wid = tid >> 5;
    if (tid == 0) carry_s = 0;
    __syncthreads();
    const int nchunks = (N_NODES + 1023) / 1024;
    for (int c = 0; c < nchunks; c++) {
        int i = c * 1024 + tid;
        int v = (i < N_NODES) ? g_count[i] : 0;
        // warp inclusive scan
        int x = v;
        #pragma unroll
        for (int o = 1; o < 32; o <<= 1) {
            int y = __shfl_up_sync(0xffffffffu, x, o);
            if (lane >= o) x += y;
        }
        if (lane == 31) warpsums[wid] = x;
        __syncthreads();
        if (tid < 32) {
            int w = warpsums[tid];
            int xx = w;
            #pragma unroll
            for (int o = 1; o < 32; o <<= 1) {
                int y = __shfl_up_sync(0xffffffffu, xx, o);
                if (tid >= o) xx += y;
            }
            warpsums[tid] = xx - w;   // exclusive warp offsets
        }
        __syncthreads();
        int incl = x + warpsums[wid];
        int excl = incl - v + carry_s;
        if (i < N_NODES) {
            g_rowstart[i] = excl;
            g_cursor[i]   = excl;
        }
        __syncthreads();
        if (tid == 1023) carry_s += incl;   // chunk total
        __syncthreads();
    }
    if (tid == 0) g_rowstart[N_NODES] = carry_s;
}

// ---------------- K5: scatter edges into CSR slots; fold s_src[src]+s_e ----------------
__global__ void k_scatter(const int* __restrict__ src, const int* __restrict__ dst) {
    int e = blockIdx.x * blockDim.x + threadIdx.x;
    if (e >= N_EDGES) return;
    int d = dst[e];
    int pos = atomicAdd(&g_cursor[d], 1);
    int s = src[e];
    g_ssidx[pos] = s;
    const float4* se = reinterpret_cast<const float4*>(&g_se[(size_t)e * NH]);
    const float4* ss = reinterpret_cast<const float4*>(&g_ssrc[s * NH]);
    float4 a0 = se[0], a1 = se[1], b0 = ss[0], b1 = ss[1];
    float4* ov = reinterpret_cast<float4*>(&g_sval[(size_t)pos * NH]);
    ov[0] = make_float4(a0.x + b0.x, a0.y + b0.y, a0.z + b0.z, a0.w + b0.w);
    ov[1] = make_float4(a1.x + b1.x, a1.y + b1.y, a1.z + b1.z, a1.w + b1.w);
}

// ---------------- K6: gather per node (warp/node): softmax-weighted sum, write out ----------------
__global__ __launch_bounds__(256) void k_gather(float* __restrict__ out) {
    int warp = (blockIdx.x * blockDim.x + threadIdx.x) >> 5;
    int lane = threadIdx.x & 31;
    if (warp >= N_NODES) return;
    int n = warp;
    int h = lane >> 2;                       // head for this lane's 4 output cols
    float sd = g_sdst[n * NH + h];
    int beg = g_rowstart[n], end = g_rowstart[n + 1];

    float4 acc = make_float4(0.f, 0.f, 0.f, 0.f);
    float z = 0.f;
    for (int i = beg; i < end; i++) {
        int s = g_ssidx[i];
        float sv = g_sval[(size_t)i * NH + h];
        float e = sv + sd;
        e = fmaxf(e, 0.2f * e);              // leaky_relu(0.2)
        float ex = __expf(e);                 // shift-invariant: no segment-max needed
        z += ex;
        float4 wv = *reinterpret_cast<const float4*>(&g_Wh[(size_t)s * OUT_F + lane * 4]);
        acc.x += ex * wv.x; acc.y += ex * wv.y;
        acc.z += ex * wv.z; acc.w += ex * wv.w;
    }
    float4 o;
    if (end > beg) {
        float inv = 1.f / z;
        o = make_float4(acc.x * inv, acc.y * inv, acc.z * inv, acc.w * inv);
    } else {
        o = make_float4(0.f, 0.f, 0.f, 0.f);
    }
    *reinterpret_cast<float4*>(&out[(size_t)n * OUT_F + lane * 4]) = o;
}

// ---------------- launch ----------------
extern "C" void kernel_launch(void* const* d_in, const int* in_sizes, int n_in,
                              void* d_out, int out_size) {
    const float* node_feats = (const float*)d_in[0];
    const float* edge_feats = (const float*)d_in[1];
    const int*   src        = (const int*)d_in[2];
    const int*   dst        = (const int*)d_in[3];
    const float* node_w     = (const float*)d_in[4];
    const float* node_b     = (const float*)d_in[5];
    const float* edge_w     = (const float*)d_in[6];
    const float* edge_b     = (const float*)d_in[7];
    const float* attn       = (const float*)d_in[8];
    float* out = (float*)d_out;

    k_init<<<160, 256>>>(edge_w, edge_b, attn);
    k_gemm<<<(N_NODES + 127) / 128, 256>>>(node_feats, node_w, node_b);
    k_scores<<<(N_NODES * NH + 255) / 256, 256>>>(attn);
    k_se<<<(N_EDGES + 255) / 256, 256>>>(edge_feats, dst);
    k_scan<<<1, 1024>>>();
    k_scatter<<<(N_EDGES + 255) / 256, 256>>>(src, dst);
    k_gather<<<(N_NODES + 7) / 8, 256>>>(out);
}

// round 3
// speedup vs baseline: 1.4235x; 1.4235x over previous
#include <cuda_runtime.h>
#include <cuda_bf16.h>
#include <cstdint>
#include <cstddef>

#define N_NODES 40000
#define N_EDGES 640000
#define IN_F    256
#define EDGE_F  64
#define OUT_F   128
#define NH      8
#define DH      16

// ---------------- scratch ----------------
__device__ __align__(16) float g_Wh[(size_t)N_NODES * OUT_F];
__device__ __align__(16) float g_ssrc[N_NODES * NH];
__device__ __align__(16) float g_sdst[N_NODES * NH];
__device__ __align__(16) float g_se[(size_t)N_EDGES * NH];
__device__ __align__(16) int2  g_slot[N_EDGES];
__device__ __align__(16) int   g_count[N_NODES];
__device__ __align__(16) int   g_rowstart[N_NODES + 1];
__device__ __align__(16) int   g_cursor[N_NODES];
__device__ float g_weff[NH * EDGE_F];
__device__ float g_beff[NH];

// ---------------- helpers ----------------
__device__ __forceinline__ uint32_t smem_u32(const void* p) {
    uint32_t a;
    asm("{ .reg .u64 t; cvta.to.shared.u64 t, %1; cvt.u32.u64 %0, t; }" : "=r"(a) : "l"(p));
    return a;
}
__device__ __forceinline__ uint32_t swz(uint32_t off) {     // SW128-style XOR swizzle
    return off ^ ((off >> 3) & 0x70);
}
__device__ __forceinline__ void ldsm4(uint32_t& r0, uint32_t& r1, uint32_t& r2, uint32_t& r3, uint32_t addr) {
    asm volatile("ldmatrix.sync.aligned.m8n8.x4.shared.b16 {%0,%1,%2,%3}, [%4];"
                 : "=r"(r0), "=r"(r1), "=r"(r2), "=r"(r3) : "r"(addr));
}
__device__ __forceinline__ void mma16816(float* c, uint32_t a0, uint32_t a1, uint32_t a2, uint32_t a3,
                                         uint32_t b0, uint32_t b1) {
    asm volatile("mma.sync.aligned.m16n8k16.row.col.f32.bf16.bf16.f32 "
                 "{%0,%1,%2,%3}, {%4,%5,%6,%7}, {%8,%9}, {%0,%1,%2,%3};"
                 : "+f"(c[0]), "+f"(c[1]), "+f"(c[2]), "+f"(c[3])
                 : "r"(a0), "r"(a1), "r"(a2), "r"(a3), "r"(b0), "r"(b1));
}
__device__ __forceinline__ uint32_t pack_bf16x2(float a, float b) {
    __nv_bfloat16 x = __float2bfloat16(a), y = __float2bfloat16(b);
    return (uint32_t)__bfloat16_as_ushort(x) | ((uint32_t)__bfloat16_as_ushort(y) << 16);
}

// ---------------- K0: zero histogram + fold attn into edge_w ----------------
__global__ void k_init(const float* __restrict__ edge_w,
                       const float* __restrict__ edge_b,
                       const float* __restrict__ attn) {
    int t = blockIdx.x * blockDim.x + threadIdx.x;
    for (int i = t; i < N_NODES; i += gridDim.x * blockDim.x) g_count[i] = 0;
    if (blockIdx.x == 0) {
        for (int i = threadIdx.x; i < NH * EDGE_F; i += blockDim.x) {
            int h = i >> 6, k = i & 63;
            float s = 0.f;
            #pragma unroll
            for (int d = 0; d < DH; d++)
                s += edge_w[(h * DH + d) * EDGE_F + k] * attn[h * 48 + 32 + d];
            g_weff[i] = s;
        }
        if (threadIdx.x < NH) {
            int h = threadIdx.x;
            float s = 0.f;
            #pragma unroll
            for (int d = 0; d < DH; d++)
                s += edge_b[h * DH + d] * attn[h * 48 + 32 + d];
            g_beff[h] = s;
        }
    }
}

// ---------------- K1: bf16-split MMA GEMM: Wh = A @ B^T + bias, fused s_src/s_dst ----------------
// block: 128(M) x 128(N), K chunks of 64; 8 warps, warp tile 32x64.
#define SMEM_GEMM 65536
__global__ __launch_bounds__(256) void k_gemm(const float* __restrict__ A,
                                              const float* __restrict__ B,
                                              const float* __restrict__ bias,
                                              const float* __restrict__ attn) {
    extern __shared__ char sm[];
    const uint32_t A_HI = 0, A_LO = 16384, B_HI = 32768, B_LO = 49152;
    uint32_t sbase = smem_u32(sm);

    int tid = threadIdx.x, w = tid >> 5, lane = tid & 31;
    int m0 = blockIdx.x * 128;
    int wm = (w >> 1) * 32, wn = (w & 1) * 64;
    int g = lane >> 2, t = lane & 3;

    float c[2][8][4];
    #pragma unroll
    for (int mt = 0; mt < 2; mt++)
        #pragma unroll
        for (int nt = 0; nt < 8; nt++)
            #pragma unroll
            for (int j = 0; j < 4; j++) c[mt][nt][j] = 0.f;

    #pragma unroll 1
    for (int chunk = 0; chunk < 4; chunk++) {
        int k0 = chunk << 6;
        // stage + split-convert A,B fp32 -> bf16 hi/lo, swizzled [row][64] layout
        #pragma unroll
        for (int i = 0; i < 8; i++) {
            int idx = tid + i * 256;          // 0..2047
            int r = idx >> 4;                 // 0..127
            int cc = (idx & 15) << 2;         // 0..60
            int m = m0 + r;
            float4 va = (m < N_NODES) ? *(const float4*)&A[(size_t)m * IN_F + k0 + cc]
                                      : make_float4(0.f, 0.f, 0.f, 0.f);
            float4 vb = *(const float4*)&B[(size_t)r * IN_F + k0 + cc];
            uint32_t o = swz((uint32_t)(r * 128 + cc * 2));
            // A hi/lo
            {
                float h0 = __bfloat162float(__float2bfloat16(va.x));
                float h1 = __bfloat162float(__float2bfloat16(va.y));
                float h2 = __bfloat162float(__float2bfloat16(va.z));
                float h3 = __bfloat162float(__float2bfloat16(va.w));
                *(uint2*)(sm + A_HI + o) = make_uint2(pack_bf16x2(h0, h1), pack_bf16x2(h2, h3));
                *(uint2*)(sm + A_LO + o) = make_uint2(pack_bf16x2(va.x - h0, va.y - h1),
                                                      pack_bf16x2(va.z - h2, va.w - h3));
            }
            // B hi/lo
            {
                float h0 = __bfloat162float(__float2bfloat16(vb.x));
                float h1 = __bfloat162float(__float2bfloat16(vb.y));
                float h2 = __bfloat162float(__float2bfloat16(vb.z));
                float h3 = __bfloat162float(__float2bfloat16(vb.w));
                *(uint2*)(sm + B_HI + o) = make_uint2(pack_bf16x2(h0, h1), pack_bf16x2(h2, h3));
                *(uint2*)(sm + B_LO + o) = make_uint2(pack_bf16x2(vb.x - h0, vb.y - h1),
                                                      pack_bf16x2(vb.z - h2, vb.w - h3));
            }
        }
        __syncthreads();

        int lr = lane & 15, lc = (lane >> 4) << 3;   // ldmatrix lane addressing
        #pragma unroll
        for (int ks = 0; ks < 4; ks++) {
            int kk = (ks << 4) + lc;
            uint32_t ao0 = swz((uint32_t)((wm + lr) * 128 + kk * 2));
            uint32_t ao1 = swz((uint32_t)((wm + 16 + lr) * 128 + kk * 2));
            uint32_t ah[2][4], al[2][4];
            ldsm4(ah[0][0], ah[0][1], ah[0][2], ah[0][3], sbase + A_HI + ao0);
            ldsm4(ah[1][0], ah[1][1], ah[1][2], ah[1][3], sbase + A_HI + ao1);
            ldsm4(al[0][0], al[0][1], al[0][2], al[0][3], sbase + A_LO + ao0);
            ldsm4(al[1][0], al[1][1], al[1][2], al[1][3], sbase + A_LO + ao1);
            #pragma unroll
            for (int np = 0; np < 4; np++) {
                uint32_t bo = swz((uint32_t)((wn + np * 16 + lr) * 128 + kk * 2));
                uint32_t bh[4], bl[4];
                ldsm4(bh[0], bh[1], bh[2], bh[3], sbase + B_HI + bo);
                ldsm4(bl[0], bl[1], bl[2], bl[3], sbase + B_LO + bo);
                #pragma unroll
                for (int mt = 0; mt < 2; mt++) {
                    // ntile = np*2 uses {b[0],b[2]}; np*2+1 uses {b[1],b[3]}
                    mma16816(c[mt][np * 2],     ah[mt][0], ah[mt][1], ah[mt][2], ah[mt][3], bh[0], bh[2]);
                    mma16816(c[mt][np * 2],     ah[mt][0], ah[mt][1], ah[mt][2], ah[mt][3], bl[0], bl[2]);
                    mma16816(c[mt][np * 2],     al[mt][0], al[mt][1], al[mt][2], al[mt][3], bh[0], bh[2]);
                    mma16816(c[mt][np * 2 + 1], ah[mt][0], ah[mt][1], ah[mt][2], ah[mt][3], bh[1], bh[3]);
                    mma16816(c[mt][np * 2 + 1], ah[mt][0], ah[mt][1], ah[mt][2], ah[mt][3], bl[1], bl[3]);
                    mma16816(c[mt][np * 2 + 1], al[mt][0], al[mt][1], al[mt][2], al[mt][3], bh[1], bh[3]);
                }
            }
        }
        __syncthreads();
    }

    // ---- epilogue: bias, store Wh, fused s_src/s_dst head reductions ----
    float as0[8], as1[8], ad0[8], ad1[8], bb0[8], bb1[8];
    #pragma unroll
    for (int nt = 0; nt < 8; nt++) {
        int col = wn + nt * 8 + t * 2;
        int h = col >> 4, d = col & 15;
        as0[nt] = attn[h * 48 + d];      as1[nt] = attn[h * 48 + d + 1];
        ad0[nt] = attn[h * 48 + 16 + d]; ad1[nt] = attn[h * 48 + 16 + d + 1];
        bb0[nt] = bias[col];             bb1[nt] = bias[col + 1];
    }
    float ps[2][2][4], pd[2][2][4];
    #pragma unroll
    for (int mt = 0; mt < 2; mt++)
        #pragma unroll
        for (int hf = 0; hf < 2; hf++)
            #pragma unroll
            for (int hh = 0; hh < 4; hh++) { ps[mt][hf][hh] = 0.f; pd[mt][hf][hh] = 0.f; }

    #pragma unroll
    for (int mt = 0; mt < 2; mt++) {
        #pragma unroll
        for (int hf = 0; hf < 2; hf++) {
            int m = m0 + wm + mt * 16 + g + hf * 8;
            bool ok = (m < N_NODES);
            #pragma unroll
            for (int nt = 0; nt < 8; nt++) {
                float v0 = c[mt][nt][hf * 2 + 0] + bb0[nt];
                float v1 = c[mt][nt][hf * 2 + 1] + bb1[nt];
                if (ok) {
                    int col = wn + nt * 8 + t * 2;
                    *(float2*)&g_Wh[(size_t)m * OUT_F + col] = make_float2(v0, v1);
                }
                ps[mt][hf][nt >> 1] += v0 * as0[nt] + v1 * as1[nt];
                pd[mt][hf][nt >> 1] += v0 * ad0[nt] + v1 * ad1[nt];
            }
        }
    }
    #pragma unroll
    for (int mt = 0; mt < 2; mt++)
        #pragma unroll
        for (int hf = 0; hf < 2; hf++)
            #pragma unroll
            for (int hh = 0; hh < 4; hh++) {
                float s = ps[mt][hf][hh], d2 = pd[mt][hf][hh];
                s += __shfl_xor_sync(0xffffffffu, s, 1);
                s += __shfl_xor_sync(0xffffffffu, s, 2);
                d2 += __shfl_xor_sync(0xffffffffu, d2, 1);
                d2 += __shfl_xor_sync(0xffffffffu, d2, 2);
                if (t == 0) {
                    int m = m0 + wm + mt * 16 + g + hf * 8;
                    if (m < N_NODES) {
                        int h = (w & 1) * 4 + hh;
                        g_ssrc[m * NH + h] = s;
                        g_sdst[m * NH + h] = d2;
                    }
                }
            }
}

// ---------------- K2: s_e + s_src fold + dst histogram (smem-staged) ----------------
__global__ __launch_bounds__(128) void k_se(const float* __restrict__ EF,
                                            const int* __restrict__ src,
                                            const int* __restrict__ dst) {
    __shared__ float xs[128 * 65];
    __shared__ float ws[NH * EDGE_F];
    __shared__ float bs[NH];
    int tid = threadIdx.x;
    for (int i = tid; i < NH * EDGE_F; i += 128) ws[i] = g_weff[i];
    if (tid < NH) bs[tid] = g_beff[tid];

    int ebase = blockIdx.x * 128;
    const float* p = EF + (size_t)ebase * EDGE_F;
    #pragma unroll
    for (int i = 0; i < 64; i++) {
        int idx = tid + i * 128;
        xs[(idx >> 6) * 65 + (idx & 63)] = p[idx];
    }
    __syncthreads();

    int e = ebase + tid;
    float acc[NH];
    #pragma unroll
    for (int h = 0; h < NH; h++) acc[h] = bs[h];
    const float* xr = &xs[tid * 65];
    #pragma unroll
    for (int gq = 0; gq < 16; gq++) {
        float x0 = xr[gq * 4], x1 = xr[gq * 4 + 1], x2 = xr[gq * 4 + 2], x3 = xr[gq * 4 + 3];
        #pragma unroll
        for (int h = 0; h < NH; h++) {
            float4 wv = *(const float4*)&ws[h * EDGE_F + gq * 4];
            acc[h] += x0 * wv.x + x1 * wv.y + x2 * wv.z + x3 * wv.w;
        }
    }
    int s = src[e], d = dst[e];
    atomicAdd(&g_count[d], 1);
    float4 s0 = *(const float4*)&g_ssrc[s * NH];
    float4 s1 = *(const float4*)&g_ssrc[s * NH + 4];
    *(float4*)&g_se[(size_t)e * NH]     = make_float4(acc[0] + s0.x, acc[1] + s0.y, acc[2] + s0.z, acc[3] + s0.w);
    *(float4*)&g_se[(size_t)e * NH + 4] = make_float4(acc[4] + s1.x, acc[5] + s1.y, acc[6] + s1.z, acc[7] + s1.w);
}

// ---------------- K3: exclusive scan ----------------
__global__ __launch_bounds__(1024) void k_scan() {
    __shared__ int wsum[32];
    __shared__ int carry_s;
    int tid = threadIdx.x, lane = tid & 31, wid = tid >> 5;
    if (tid == 0) carry_s = 0;
    __syncthreads();
    #pragma unroll 1
    for (int cch = 0; cch < (N_NODES + 4095) / 4096; cch++) {
        int base = cch * 4096 + tid * 4;
        int4 v = make_int4(0, 0, 0, 0);
        if (base < N_NODES) v = *(const int4*)&g_count[base];
        int s0 = v.x, s1 = s0 + v.y, s2 = s1 + v.z, s3 = s2 + v.w;
        int x = s3;
        #pragma unroll
        for (int o = 1; o < 32; o <<= 1) {
            int y = __shfl_up_sync(0xffffffffu, x, o);
            if (lane >= o) x += y;
        }
        if (lane == 31) wsum[wid] = x;
        __syncthreads();
        if (wid == 0) {
            int wv = wsum[lane], xx = wv;
            #pragma unroll
            for (int o = 1; o < 32; o <<= 1) {
                int y = __shfl_up_sync(0xffffffffu, xx, o);
                if (lane >= o) xx += y;
            }
            wsum[lane] = xx - wv;
        }
        __syncthreads();
        int excl = (x - s3) + wsum[wid] + carry_s;
        if (base < N_NODES) {
            int4 rs = make_int4(excl, excl + s0, excl + s1, excl + s2);
            *(int4*)&g_rowstart[base] = rs;
            *(int4*)&g_cursor[base]   = rs;
        }
        __syncthreads();
        if (tid == 1023) carry_s += x + wsum[31];
        __syncthreads();
    }
    if (threadIdx.x == 0) g_rowstart[N_NODES] = carry_s;
}

// ---------------- K4: scatter ----------------
__global__ void k_scatter(const int* __restrict__ src, const int* __restrict__ dst) {
    int e = blockIdx.x * blockDim.x + threadIdx.x;
    if (e >= N_EDGES) return;
    int d = dst[e];
    int pos = atomicAdd(&g_cursor[d], 1);
    g_slot[pos] = make_int2(src[e], e);
}

// ---------------- K5: gather per node (warp/node) ----------------
__global__ __launch_bounds__(256) void k_gather(float* __restrict__ out) {
    int warp = (blockIdx.x * blockDim.x + threadIdx.x) >> 5;
    int lane = threadIdx.x & 31;
    if (warp >= N_NODES) return;
    int h = lane >> 2;
    float sd = g_sdst[warp * NH + h];
    int beg = g_rowstart[warp], end = g_rowstart[warp + 1];
    float4 acc = make_float4(0.f, 0.f, 0.f, 0.f);
    float z = 0.f;
    for (int i = beg; i < end; i++) {
        int2 sl = g_slot[i];
        float sv = g_se[(size_t)sl.y * NH + h] + sd;
        sv = fmaxf(sv, 0.2f * sv);
        float ex = __expf(sv);
        z += ex;
        float4 wv = *(const float4*)&g_Wh[(size_t)sl.x * OUT_F + lane * 4];
        acc.x += ex * wv.x; acc.y += ex * wv.y;
        acc.z += ex * wv.z; acc.w += ex * wv.w;
    }
    float4 o = make_float4(0.f, 0.f, 0.f, 0.f);
    if (end > beg) {
        float inv = 1.f / z;
        o = make_float4(acc.x * inv, acc.y * inv, acc.z * inv, acc.w * inv);
    }
    *(float4*)&out[(size_t)warp * OUT_F + lane * 4] = o;
}

// ---------------- launch ----------------
extern "C" void kernel_launch(void* const* d_in, const int* in_sizes, int n_in,
                              void* d_out, int out_size) {
    const float* node_feats = (const float*)d_in[0];
    const float* edge_feats = (const float*)d_in[1];
    const int*   src        = (const int*)d_in[2];
    const int*   dst        = (const int*)d_in[3];
    const float* node_w     = (const float*)d_in[4];
    const float* node_b     = (const float*)d_in[5];
    const float* edge_w     = (const float*)d_in[6];
    const float* edge_b     = (const float*)d_in[7];
    const float* attn       = (const float*)d_in[8];
    float* out = (float*)d_out;

    cudaFuncSetAttribute(k_gemm, cudaFuncAttributeMaxDynamicSharedMemorySize, SMEM_GEMM);

    k_init<<<160, 256>>>(edge_w, edge_b, attn);
    k_gemm<<<(N_NODES + 127) / 128, 256, SMEM_GEMM>>>(node_feats, node_w, node_b, attn);
    k_se<<<N_EDGES / 128, 128>>>(edge_feats, src, dst);
    k_scan<<<1, 1024>>>();
    k_scatter<<<(N_EDGES + 255) / 256, 256>>>(src, dst);
    k_gather<<<(N_NODES * 32 + 255) / 256, 256>>>(out);
}